// round 1
// baseline (speedup 1.0000x reference)
#include <cuda_runtime.h>
#include <cuda_bf16.h>

// CustomAttention: out[b,n] = b0 * sum_m tanh(a0 * x[b,n]*x[b,m]) * x[b,m]
// B=16, N=4096. Fused: never materialize the [B,N,N] intermediate.
// Transcendental-bound: 268M tanh evals -> MUFU.TANH via tanh.approx.f32.

#define NBATCH 16
#define NDIM   4096
#define BT     64      // threads per block (one output element per thread)

__device__ __forceinline__ float tanh_fast(float v) {
    float r;
    asm("tanh.approx.f32 %0, %1;" : "=f"(r) : "f"(v));
    return r;
}

__global__ __launch_bounds__(BT)
void custom_attention_kernel(const float* __restrict__ x,
                             const float* __restrict__ a,
                             const float* __restrict__ b,
                             float* __restrict__ out)
{
    __shared__ float xs[NDIM];   // one batch row, 16 KB

    const int batch = blockIdx.y;
    const float* __restrict__ xb = x + batch * NDIM;

    // Cooperative row load, float4 vectorized: 1024 float4 / 64 threads = 16 each
    const float4* __restrict__ xb4 = reinterpret_cast<const float4*>(xb);
    float4* xs4 = reinterpret_cast<float4*>(xs);
    #pragma unroll
    for (int i = threadIdx.x; i < NDIM / 4; i += BT) {
        xs4[i] = xb4[i];
    }
    __syncthreads();

    const int n  = blockIdx.x * BT + threadIdx.x;
    const float xn = xs[n];
    const float c  = a[0] * xn;          // tanh argument scale for this row

    float acc0 = 0.f, acc1 = 0.f;        // two chains to relax FFMA RAW latency

    #pragma unroll 4
    for (int m4 = 0; m4 < NDIM / 4; m4 += 2) {
        // float4 SMEM reads: all lanes same address -> broadcast, conflict-free
        float4 v0 = xs4[m4];
        float4 v1 = xs4[m4 + 1];
        acc0 = fmaf(tanh_fast(c * v0.x), v0.x, acc0);
        acc1 = fmaf(tanh_fast(c * v0.y), v0.y, acc1);
        acc0 = fmaf(tanh_fast(c * v0.z), v0.z, acc0);
        acc1 = fmaf(tanh_fast(c * v0.w), v0.w, acc1);
        acc0 = fmaf(tanh_fast(c * v1.x), v1.x, acc0);
        acc1 = fmaf(tanh_fast(c * v1.y), v1.y, acc1);
        acc0 = fmaf(tanh_fast(c * v1.z), v1.z, acc0);
        acc1 = fmaf(tanh_fast(c * v1.w), v1.w, acc1);
    }

    out[batch * NDIM + n] = b[0] * (acc0 + acc1);
}

extern "C" void kernel_launch(void* const* d_in, const int* in_sizes, int n_in,
                              void* d_out, int out_size)
{
    const float* x = (const float*)d_in[0];   // [16, 4096] fp32
    const float* a = (const float*)d_in[1];   // [1]
    const float* b = (const float*)d_in[2];   // [1]
    float* out = (float*)d_out;               // [16, 4096] fp32

    dim3 grid(NDIM / BT, NBATCH);             // 64 x 16 = 1024 blocks
    custom_attention_kernel<<<grid, BT>>>(x, a, b, out);
}